// round 2
// baseline (speedup 1.0000x reference)
#include <cuda_runtime.h>
#include <cstdint>

// Problem constants (fixed by setup_inputs)
#define BATCH   8
#define HH      256
#define WW      256
#define NPATCH  64      // 8x8 grid of 32x32 patches
#define EPSBN   1e-5f
// conv_weights per (b,p) block layout
#define ABLK    110592  // total floats per (b,p)
#define WOFF2   36864   // offset of layer-2 dynamic weights  (64*9*64)

// ---------------- scratch (static device globals; no allocation) -------------
__device__ float g_y1[(size_t)BATCH * 128 * HH * WW];  // layer-1 pre-BN output (256 MiB)
__device__ float g_sum1[128], g_sqs1[128];
__device__ float g_sum2[128], g_sqs2[128];
__device__ float g_a1[128], g_b1[128];                 // BN1 folded scale/bias
__device__ float g_a2[128], g_b2[128];

// ---------------- kernels ----------------------------------------------------

__global__ void zero_stats_kernel() {
    int t = threadIdx.x;
    if (t < 128) {
        g_sum1[t] = 0.f; g_sqs1[t] = 0.f;
        g_sum2[t] = 0.f; g_sqs2[t] = 0.f;
    }
}

// One CTA: (b, patch, group of 32 output channels). 512 threads.
// Thread tile: 4 oc x 16 px. Pixel tile: 32x32 patch; pxg -> (row, half-row).
// CIN processed in chunks of 8 channels held in smem with a 1-halo (34x34).
template<int CIN, int WOFF, int LAYER>
__global__ void __launch_bounds__(512, 1)
conv_kernel(const float* __restrict__ xin,
            const float* __restrict__ wsh,     // shared conv weights [64,CIN,3,3]
            const float* __restrict__ cwall,   // conv_weights [B,64,ABLK]
            float* __restrict__ dout)          // used when LAYER==2
{
    __shared__ float s_in[8][34][35];      // 38080 B, stride 35 => conflict-free
    __shared__ float s_w[8 * 9 * 32];      // [ci][k][oc], 9216 B

    const int blk   = blockIdx.x;
    const int b     = blk >> 8;            // 256 blocks per batch
    const int rem   = blk & 255;
    const int patch = rem >> 2;
    const int oc_base = (rem & 3) << 5;    // 0,32,64,96
    const int y0 = (patch >> 3) << 5;
    const int x0 = (patch & 7) << 5;

    const int tid   = threadIdx.x;
    const int pxg   = tid & 63;
    const int row   = pxg >> 1;            // 0..31
    const int col0  = (pxg & 1) << 4;      // 0 or 16
    const int oc_loc = (tid >> 6) << 2;    // 0,4,...,28

    const float* src = (LAYER == 1) ? xin : g_y1;
    float*       dst = (LAYER == 1) ? g_y1 : dout;

    float acc[4][16];
    #pragma unroll
    for (int i = 0; i < 4; ++i)
        #pragma unroll
        for (int j = 0; j < 16; ++j) acc[i][j] = 0.f;

    const size_t cw_base = (size_t)(b * NPATCH + patch) * ABLK + WOFF;

    for (int cc = 0; cc < CIN / 8; ++cc) {
        __syncthreads();
        // ---- load 8-channel input halo tile (34x34 each) ----
        for (int idx = tid; idx < 8 * 34 * 34; idx += 512) {
            int ci = idx / 1156;
            int r  = (idx - ci * 1156) / 34;
            int c  = idx - ci * 1156 - r * 34;
            int gy = y0 - 1 + r, gx = x0 - 1 + c;
            float v = 0.f;
            int cig = cc * 8 + ci;
            if ((unsigned)gy < 256u && (unsigned)gx < 256u) {
                v = src[(((size_t)b * CIN + cig) * HH + gy) * WW + gx];
                if (LAYER == 2) v = fmaxf(0.f, fmaf(g_a1[cig], v, g_b1[cig]));
            }
            s_in[ci][r][c] = v;
        }
        // ---- load weights for this oc group: layout [ci*9+k][oc] ----
        for (int idx = tid; idx < 2304; idx += 512) {
            int q  = idx >> 5;              // ci*9 + k
            int oc = idx & 31;
            int ci = q / 9, k = q - ci * 9;
            int cig = cc * 8 + ci;
            int ocA = oc_base + oc;
            float wv;
            if (ocA < 64)
                wv = wsh[((size_t)ocA * CIN + cig) * 9 + k];
            else
                wv = cwall[cw_base + ((size_t)(ocA - 64) * CIN + cig) * 9 + k];
            s_w[idx] = wv;
        }
        __syncthreads();
        // ---- FMA core ----
        #pragma unroll 2
        for (int ci = 0; ci < 8; ++ci) {
            #pragma unroll
            for (int ky = 0; ky < 3; ++ky) {
                float vbuf[18];
                const float* ip = &s_in[ci][row + ky][col0];
                #pragma unroll
                for (int j = 0; j < 18; ++j) vbuf[j] = ip[j];
                #pragma unroll
                for (int kx = 0; kx < 3; ++kx) {
                    float4 w4 = *(const float4*)&s_w[(((ci * 3 + ky) * 3 + kx) << 5) + oc_loc];
                    #pragma unroll
                    for (int j = 0; j < 16; ++j) {
                        float v = vbuf[j + kx];
                        acc[0][j] = fmaf(w4.x, v, acc[0][j]);
                        acc[1][j] = fmaf(w4.y, v, acc[1][j]);
                        acc[2][j] = fmaf(w4.z, v, acc[2][j]);
                        acc[3][j] = fmaf(w4.w, v, acc[3][j]);
                    }
                }
            }
        }
    }

    // ---- write out + per-channel sum/sumsq (warp-uniform oc) ----
    float* gsum = (LAYER == 1) ? g_sum1 : g_sum2;
    float* gsqs = (LAYER == 1) ? g_sqs1 : g_sqs2;
    #pragma unroll
    for (int i = 0; i < 4; ++i) {
        int oc = oc_base + oc_loc + i;
        size_t base = (((size_t)b * 128 + oc) * HH + (y0 + row)) * WW + x0 + col0;
        float ls = 0.f, lq = 0.f;
        #pragma unroll
        for (int j = 0; j < 16; ++j) {
            float v = acc[i][j];
            ls += v; lq = fmaf(v, v, lq);
            dst[base + j] = v;
        }
        #pragma unroll
        for (int off = 16; off; off >>= 1) {
            ls += __shfl_down_sync(0xffffffffu, ls, off);
            lq += __shfl_down_sync(0xffffffffu, lq, off);
        }
        if ((tid & 31) == 0) {
            atomicAdd(&gsum[oc], ls);
            atomicAdd(&gsqs[oc], lq);
        }
    }
}

__global__ void finalize_stats_kernel(const float* __restrict__ gamma,
                                      const float* __restrict__ beta,
                                      int layer)
{
    int c = threadIdx.x;
    if (c >= 128) return;
    const float invN = 1.f / (float)((size_t)BATCH * HH * WW);
    float s = (layer == 1) ? g_sum1[c] : g_sum2[c];
    float q = (layer == 1) ? g_sqs1[c] : g_sqs2[c];
    float m   = s * invN;
    float var = fmaf(-m, m, q * invN);
    float inv = rsqrtf(var + EPSBN);
    float a   = gamma[c] * inv;
    float bb  = fmaf(-a, m, beta[c]);
    if (layer == 1) { g_a1[c] = a; g_b1[c] = bb; }
    else            { g_a2[c] = a; g_b2[c] = bb; }
}

__global__ void apply_bn2_kernel(float4* __restrict__ out)
{
    const size_t n4 = (size_t)BATCH * 128 * HH * WW / 4;   // 16777216
    for (size_t i = (size_t)blockIdx.x * blockDim.x + threadIdx.x; i < n4;
         i += (size_t)gridDim.x * blockDim.x) {
        int c = (int)((i >> 14) & 127);                    // 16384 float4 per (b,c) image
        float a = g_a2[c], bb = g_b2[c];
        float4 v = out[i];
        v.x = fmaxf(0.f, fmaf(a, v.x, bb));
        v.y = fmaxf(0.f, fmaf(a, v.y, bb));
        v.z = fmaxf(0.f, fmaf(a, v.z, bb));
        v.w = fmaxf(0.f, fmaf(a, v.w, bb));
        out[i] = v;
    }
}

// ---------------- launcher ----------------------------------------------------
extern "C" void kernel_launch(void* const* d_in, const int* in_sizes, int n_in,
                              void* d_out, int out_size)
{
    const float* x      = (const float*)d_in[0];  // [8,64,256,256]
    const float* cw     = (const float*)d_in[1];  // [8,64,110592]
    const float* w1     = (const float*)d_in[2];  // [64,64,3,3]
    const float* w2     = (const float*)d_in[3];  // [64,128,3,3]
    const float* gamma1 = (const float*)d_in[4];
    const float* beta1  = (const float*)d_in[5];
    const float* gamma2 = (const float*)d_in[6];
    const float* beta2  = (const float*)d_in[7];
    float* out = (float*)d_out;

    zero_stats_kernel<<<1, 128>>>();

    // Layer 1: conv (shared ch 0-63, dynamic ch 64-127) -> g_y1 + stats1
    conv_kernel<64, 0, 1><<<BATCH * NPATCH * 4, 512>>>(x, w1, cw, nullptr);
    finalize_stats_kernel<<<1, 128>>>(gamma1, beta1, 1);

    // Layer 2: reads g_y1 with fused BN1+ReLU at load -> d_out (pre-BN) + stats2
    conv_kernel<128, WOFF2, 2><<<BATCH * NPATCH * 4, 512>>>(nullptr, w2, cw, out);
    finalize_stats_kernel<<<1, 128>>>(gamma2, beta2, 2);

    // BN2 + ReLU in place on d_out
    apply_bn2_kernel<<<8192, 256>>>((float4*)out);
}